// round 7
// baseline (speedup 1.0000x reference)
#include <cuda_runtime.h>
#include <cuda_bf16.h>
#include <cstdint>
#include <cstddef>

// ---------------------------------------------------------------------------
// Problem constants
// ---------------------------------------------------------------------------
namespace cfg {
constexpr int B   = 4;
constexpr int Hn  = 160, Wn = 288;      // input H, W
constexpr int HOo = 80,  WOo = 144;     // output H, W (stride 2)
constexpr int HW  = HOo * WOo;          // 11520
constexpr int HWin = Hn * Wn;           // 46080
constexpr int Dd  = 24;                 // disparity levels
constexpr int G_CI = 96, G_CO = 192;
constexpr int NCHUNK = 27;              // conv: 27 chunks of 32 k (tap-major)
constexpr int MT = 128;                 // pixels per CTA
}

// Scratch (static device globals — no allocation allowed)
__device__ float d_y1 [(size_t)cfg::B * cfg::G_CO * cfg::HW];   // 35.4 MB
__device__ float d_g8x[(size_t)cfg::B * cfg::G_CI * cfg::HW];   // 17.7 MB
__device__ float d_y2 [(size_t)cfg::B * 24 * cfg::HW];          //  4.4 MB
__device__ float d_c8x[(size_t)cfg::B * 12 * cfg::HW];          //  2.2 MB
__device__ float d_msk[(size_t)cfg::B * 144 * cfg::HW];         // 26.5 MB (gwc logits)
// Combined pre-split bf16 conv weights: [chunk 27] blobs of 30720B
//   blob = [hi: 192 rows x 40 bf16][lo: 192 rows x 40 bf16]
__device__ uint4 d_wB[(size_t)cfg::NCHUNK * 1920];
// Pre-split bf16 mask weights: [chunk 6] blobs of 23040B (hi 144x40 | lo 144x40)
__device__ uint4 d_wM[(size_t)6 * 1440];

// ---------------------------------------------------------------------------
// PTX helpers (sm_80-compatible only: ldmatrix / mma.sync / cp.async)
// ---------------------------------------------------------------------------
__device__ __forceinline__ uint32_t smem_u32(const void* p) {
    uint32_t a;
    asm("{ .reg .u64 t; cvta.to.shared.u64 t, %1; cvt.u32.u64 %0, t; }" : "=r"(a) : "l"(p));
    return a;
}
__device__ __forceinline__ void ldsm4(uint32_t* r, uint32_t addr) {
    asm volatile("ldmatrix.sync.aligned.m8n8.x4.shared.b16 {%0,%1,%2,%3}, [%4];"
        : "=r"(r[0]), "=r"(r[1]), "=r"(r[2]), "=r"(r[3]) : "r"(addr));
}
__device__ __forceinline__ void mma_bf16(float* c, const uint32_t* a, const uint32_t* b) {
    asm volatile(
        "mma.sync.aligned.m16n8k16.row.col.f32.bf16.bf16.f32 "
        "{%0,%1,%2,%3}, {%4,%5,%6,%7}, {%8,%9}, {%0,%1,%2,%3};"
        : "+f"(c[0]), "+f"(c[1]), "+f"(c[2]), "+f"(c[3])
        : "r"(a[0]), "r"(a[1]), "r"(a[2]), "r"(a[3]), "r"(b[0]), "r"(b[1]));
}
#define CP_ASYNC16(dst, src) \
    asm volatile("cp.async.cg.shared.global [%0], [%1], 16;" :: "r"(dst), "l"(src) : "memory")
#define CP_COMMIT()  asm volatile("cp.async.commit_group;" ::: "memory")
#define CP_WAIT0()   asm volatile("cp.async.wait_group 0;" ::: "memory")

__device__ __forceinline__ void bf16_split(float v, uint16_t& h, uint16_t& l) {
    __nv_bfloat16 hb = __float2bfloat16_rn(v);
    __nv_bfloat16 lb = __float2bfloat16_rn(v - __bfloat162float(hb));
    h = __bfloat16_as_ushort(hb);
    l = __bfloat16_as_ushort(lb);
}

// ---------------------------------------------------------------------------
// Kernel 0a: conv weight prep (combined 192-row blobs).
// chunk = tap*3 + ci/32; blob = [hi 192x40 | lo 192x40] bf16.
// ---------------------------------------------------------------------------
__global__ void wprep_kernel(const float* __restrict__ w) {
    using namespace cfg;
    int idx = blockIdx.x * blockDim.x + threadIdx.x;
    if (idx >= NCHUNK * 192 * 32) return;
    int k = idx & 31, co = (idx >> 5) % 192, c = idx / (32 * 192);
    int tap = c / 3, ci = (c % 3) * 32 + k;
    float v = w[(size_t)(co * G_CI + ci) * 9 + tap];
    uint16_t hi, lo; bf16_split(v, hi, lo);
    uint16_t* blob = (uint16_t*)d_wB + (size_t)c * 15360;
    blob[co * 40 + k]        = hi;
    blob[7680 + co * 40 + k] = lo;
}

// ---------------------------------------------------------------------------
// Kernel 0b: gwc mask (1x1) weight prep. 6 chunks of 32 k; rows 40 bf16.
// ---------------------------------------------------------------------------
__global__ void wprep2_kernel(const float* __restrict__ w2) {
    using namespace cfg;
    int idx = blockIdx.x * blockDim.x + threadIdx.x;
    if (idx >= 6 * 144 * 32) return;
    int k = idx & 31, co = (idx >> 5) % 144, c = idx / (32 * 144);
    int ci = c * 32 + k;
    float v = w2[(size_t)co * 192 + ci];
    uint16_t hi, lo; bf16_split(v, hi, lo);
    uint16_t* blob = (uint16_t*)d_wM + (size_t)c * 11520;
    blob[co * 40 + k]        = hi;
    blob[5760 + co * 40 + k] = lo;
}

// ---------------------------------------------------------------------------
// Kernel 1: conv3x3 s2 p1 (96->192) + BN + leakyReLU, implicit GEMM with
// mma.sync bf16 hi/lo (3-pass). CTA: 128 px x FULL 192 co, 16 warps (4Mx4N),
// warp tile 32x48. One CTA stages A once for all 192 channels.
// smem: 2 x [Ahi 10240 | Alo 10240 | Bhi 15360 | Blo 15360] + BN 1536
// ---------------------------------------------------------------------------
static constexpr int BUF2    = 51200;
static constexpr int SM_BN2  = 2 * BUF2;                  // 102400
static constexpr int SM_CONV = SM_BN2 + 1536;             // 103936

__global__ void __launch_bounds__(512, 1)
conv_gwc_mma(const float* __restrict__ x,
             const float* __restrict__ bng, const float* __restrict__ bnb,
             const float* __restrict__ bnm, const float* __restrict__ bnv,
             float* __restrict__ y)
{
    using namespace cfg;
    extern __shared__ char smem[];
    const uint32_t sb = smem_u32(smem);
    const int t = threadIdx.x, lane = t & 31, wid = t >> 5;
    const int wm = wid & 3, wn = wid >> 2;        // wn 0..3 -> 4 x 48 co

    float* sc_s = (float*)(smem + SM_BN2);
    float* bi_s = (float*)(smem + SM_BN2 + 768);
    if (t < 192) {
        const float sc = bng[t] * rsqrtf(bnv[t] + 1e-5f);
        sc_s[t] = sc;
        bi_s[t] = bnb[t] - bnm[t] * sc;
    }

    const int pl = t & 127, kq = t >> 7;          // kq 0..3: 8 k-values each
    const int p  = blockIdx.x * MT + pl;
    const int b  = p / HW;
    const int q  = p - b * HW;
    const int ho = q / WOo, wo = q - ho * WOo;
    const float* xb = x + (size_t)b * G_CI * HWin;

    const uint32_t a_off = (uint32_t)((lane & 7) + ((lane >> 3) & 1) * 8) * 80
                         + ((lane >> 4) << 4);
    const uint32_t b_off = (uint32_t)(((lane >> 4) * 8) + (lane & 7)) * 80
                         + (((lane >> 3) & 1) << 4);

    float acc[2][6][4];
    #pragma unroll
    for (int i = 0; i < 2; i++)
        #pragma unroll
        for (int j = 0; j < 6; j++)
            #pragma unroll
            for (int r = 0; r < 4; r++) acc[i][j][r] = 0.f;

    auto ldgA = [&](int c, float* v) {
        const int tap = c / 3, dy = tap / 3, dx = tap - dy * 3;
        const int ci0 = (c - tap * 3) * 32 + kq * 8;
        const int h2 = 2 * ho - 1 + dy, w2 = 2 * wo - 1 + dx;
        const bool vr = ((unsigned)h2 < (unsigned)Hn) && ((unsigned)w2 < (unsigned)Wn);
        const float* xp = xb + (size_t)h2 * Wn + w2 + (size_t)ci0 * HWin;
        #pragma unroll
        for (int i = 0; i < 8; i++) v[i] = vr ? xp[(size_t)i * HWin] : 0.f;
    };
    auto stsA = [&](uint32_t bufb, const float* v) {
        uint32_t hp[4], lp[4];
        #pragma unroll
        for (int i = 0; i < 4; i++) {
            uint16_t h0, l0, h1, l1;
            bf16_split(v[2*i], h0, l0);
            bf16_split(v[2*i+1], h1, l1);
            hp[i] = (uint32_t)h0 | ((uint32_t)h1 << 16);
            lp[i] = (uint32_t)l0 | ((uint32_t)l1 << 16);
        }
        const uint32_t off = (uint32_t)pl * 80 + kq * 16;
        *(uint4*)(smem + bufb + off)         = make_uint4(hp[0], hp[1], hp[2], hp[3]);
        *(uint4*)(smem + bufb + 10240 + off) = make_uint4(lp[0], lp[1], lp[2], lp[3]);
    };
    auto cpB = [&](int c, uint32_t bufb) {
        const char* src = (const char*)d_wB + (size_t)c * 30720;
        const uint32_t dst = sb + bufb + 20480;
        for (int j = t; j < 1920; j += 512)
            CP_ASYNC16(dst + j * 16, src + (size_t)j * 16);
        CP_COMMIT();
    };

    {
        cpB(0, 0);
        float v0[8];
        ldgA(0, v0);
        stsA(0, v0);
        CP_WAIT0();
    }
    __syncthreads();

    float vnext[8];
    for (int c = 0; c < NCHUNK; c++) {
        const uint32_t bufb  = (uint32_t)(c & 1) * BUF2;
        const uint32_t nbufb = (uint32_t)((c + 1) & 1) * BUF2;
        const bool more = (c + 1 < NCHUNK);
        if (more) { cpB(c + 1, nbufb); ldgA(c + 1, vnext); }

        const uint32_t Ah = sb + bufb, Al = Ah + 10240;
        const uint32_t Bh = sb + bufb + 20480, Bl = Bh + 15360;
        #pragma unroll
        for (int ks = 0; ks < 2; ks++) {
            uint32_t ah[2][4], al[2][4], bb[3][4];
            #pragma unroll
            for (int ma = 0; ma < 2; ma++) {
                const uint32_t ro = (uint32_t)(wm * 32 + ma * 16) * 80 + ks * 32 + a_off;
                ldsm4(ah[ma], Ah + ro);
                ldsm4(al[ma], Al + ro);
            }
            #pragma unroll
            for (int n2 = 0; n2 < 3; n2++) {
                const uint32_t ro = (uint32_t)(wn * 48 + n2 * 16) * 80 + ks * 32 + b_off;
                ldsm4(bb[n2], Bh + ro);
            }
            #pragma unroll
            for (int ma = 0; ma < 2; ma++)
                #pragma unroll
                for (int n2 = 0; n2 < 3; n2++) {
                    mma_bf16(acc[ma][2*n2],   ah[ma], bb[n2]);
                    mma_bf16(acc[ma][2*n2+1], ah[ma], bb[n2] + 2);
                    mma_bf16(acc[ma][2*n2],   al[ma], bb[n2]);
                    mma_bf16(acc[ma][2*n2+1], al[ma], bb[n2] + 2);
                }
            #pragma unroll
            for (int n2 = 0; n2 < 3; n2++) {
                const uint32_t ro = (uint32_t)(wn * 48 + n2 * 16) * 80 + ks * 32 + b_off;
                ldsm4(bb[n2], Bl + ro);
            }
            #pragma unroll
            for (int ma = 0; ma < 2; ma++)
                #pragma unroll
                for (int n2 = 0; n2 < 3; n2++) {
                    mma_bf16(acc[ma][2*n2],   ah[ma], bb[n2]);
                    mma_bf16(acc[ma][2*n2+1], ah[ma], bb[n2] + 2);
                }
        }

        if (more) { stsA(nbufb, vnext); CP_WAIT0(); }
        __syncthreads();
    }

    // ---- epilogue: BN + leaky relu, scalar stores ----
    {
        const int bt = (blockIdx.x * MT) / HW;          // tile never straddles b
        const int q0 = blockIdx.x * MT - bt * HW;
        float* yb = y + (size_t)bt * G_CO * HW + q0;
        const int t4 = lane >> 2, tp = (lane & 3) * 2;
        #pragma unroll
        for (int ma = 0; ma < 2; ma++) {
            const int r = wm * 32 + ma * 16 + t4;
            #pragma unroll
            for (int na = 0; na < 6; na++) {
                const int co = wn * 48 + na * 8 + tp;   // 0..191
                const float s0 = sc_s[co], b0 = bi_s[co];
                const float s1 = sc_s[co + 1], b1 = bi_s[co + 1];
                float v00 = fmaf(acc[ma][na][0], s0, b0);
                float v01 = fmaf(acc[ma][na][1], s1, b1);
                float v10 = fmaf(acc[ma][na][2], s0, b0);
                float v11 = fmaf(acc[ma][na][3], s1, b1);
                v00 = (v00 >= 0.f) ? v00 : 0.1f * v00;
                v01 = (v01 >= 0.f) ? v01 : 0.1f * v01;
                v10 = (v10 >= 0.f) ? v10 : 0.1f * v10;
                v11 = (v11 >= 0.f) ? v11 : 0.1f * v11;
                yb[(size_t)co * HW + r]           = v00;
                yb[(size_t)(co + 1) * HW + r]     = v01;
                yb[(size_t)co * HW + r + 8]       = v10;
                yb[(size_t)(co + 1) * HW + r + 8] = v11;
            }
        }
    }
}

// ---------------------------------------------------------------------------
// Kernel 2: gwc mask logits GEMM: msk[144, px] = w2[144,192] . y1[192, px].
// CTA: 128 px x 144 co, 12 warps (4M x 3N), warp tile 32x48.
// ---------------------------------------------------------------------------
static constexpr int LBUF   = 43520;
static constexpr int SM_LOG = 2 * LBUF;                   // 87040

__global__ void __launch_bounds__(384, 1)
gemm_logits_mma(const float* __restrict__ y, float* __restrict__ msk)
{
    using namespace cfg;
    extern __shared__ char smem[];
    const uint32_t sb = smem_u32(smem);
    const int t = threadIdx.x, lane = t & 31, wid = t >> 5;
    const int wm = wid & 3, wn = wid >> 2;        // wn 0..2

    const int pl = t & 127, kh = t >> 7;          // kh 0..2; only kh<2 stage A
    const int p  = blockIdx.x * MT + pl;
    const int b  = p / HW;
    const int q  = p - b * HW;
    const float* yb = y + (size_t)b * G_CO * HW + q;

    const uint32_t a_off = (uint32_t)((lane & 7) + ((lane >> 3) & 1) * 8) * 80
                         + ((lane >> 4) << 4);
    const uint32_t b_off = (uint32_t)(((lane >> 4) * 8) + (lane & 7)) * 80
                         + (((lane >> 3) & 1) << 4);

    float acc[2][6][4];
    #pragma unroll
    for (int i = 0; i < 2; i++)
        #pragma unroll
        for (int j = 0; j < 6; j++)
            #pragma unroll
            for (int r = 0; r < 4; r++) acc[i][j][r] = 0.f;

    auto ldgA = [&](int c, float* v) {
        const float* yp = yb + (size_t)(c * 32 + kh * 16) * HW;
        #pragma unroll
        for (int i = 0; i < 16; i++) v[i] = yp[(size_t)i * HW];
    };
    auto stsA = [&](uint32_t bufb, const float* v) {
        uint32_t hp[8], lp[8];
        #pragma unroll
        for (int i = 0; i < 8; i++) {
            uint16_t h0, l0, h1, l1;
            bf16_split(v[2*i], h0, l0);
            bf16_split(v[2*i+1], h1, l1);
            hp[i] = (uint32_t)h0 | ((uint32_t)h1 << 16);
            lp[i] = (uint32_t)l0 | ((uint32_t)l1 << 16);
        }
        const uint32_t off = (uint32_t)pl * 80 + kh * 32;
        *(uint4*)(smem + bufb + off)           = make_uint4(hp[0], hp[1], hp[2], hp[3]);
        *(uint4*)(smem + bufb + off + 16)      = make_uint4(hp[4], hp[5], hp[6], hp[7]);
        *(uint4*)(smem + bufb + 10240 + off)      = make_uint4(lp[0], lp[1], lp[2], lp[3]);
        *(uint4*)(smem + bufb + 10240 + off + 16) = make_uint4(lp[4], lp[5], lp[6], lp[7]);
    };
    auto cpB = [&](int c, uint32_t bufb) {
        const char* src = (const char*)d_wM + (size_t)c * 23040;
        const uint32_t dst = sb + bufb + 20480;
        for (int j = t; j < 1440; j += 384)
            CP_ASYNC16(dst + j * 16, src + (size_t)j * 16);
        CP_COMMIT();
    };

    {
        cpB(0, 0);
        if (kh < 2) {
            float v0[16];
            ldgA(0, v0);
            stsA(0, v0);
        }
        CP_WAIT0();
    }
    __syncthreads();

    float vnext[16];
    for (int c = 0; c < 6; c++) {
        const uint32_t bufb  = (uint32_t)(c & 1) * LBUF;
        const uint32_t nbufb = (uint32_t)((c + 1) & 1) * LBUF;
        const bool more = (c + 1 < 6);
        if (more) { cpB(c + 1, nbufb); if (kh < 2) ldgA(c + 1, vnext); }

        const uint32_t Ah = sb + bufb, Al = Ah + 10240;
        const uint32_t Bh = sb + bufb + 20480, Bl = Bh + 11520;
        #pragma unroll
        for (int ks = 0; ks < 2; ks++) {
            uint32_t ah[2][4], al[2][4], bb[3][4];
            #pragma unroll
            for (int ma = 0; ma < 2; ma++) {
                const uint32_t ro = (uint32_t)(wm * 32 + ma * 16) * 80 + ks * 32 + a_off;
                ldsm4(ah[ma], Ah + ro);
                ldsm4(al[ma], Al + ro);
            }
            #pragma unroll
            for (int n2 = 0; n2 < 3; n2++) {
                const uint32_t ro = (uint32_t)(wn * 48 + n2 * 16) * 80 + ks * 32 + b_off;
                ldsm4(bb[n2], Bh + ro);
            }
            #pragma unroll
            for (int ma = 0; ma < 2; ma++)
                #pragma unroll
                for (int n2 = 0; n2 < 3; n2++) {
                    mma_bf16(acc[ma][2*n2],   ah[ma], bb[n2]);
                    mma_bf16(acc[ma][2*n2+1], ah[ma], bb[n2] + 2);
                    mma_bf16(acc[ma][2*n2],   al[ma], bb[n2]);
                    mma_bf16(acc[ma][2*n2+1], al[ma], bb[n2] + 2);
                }
            #pragma unroll
            for (int n2 = 0; n2 < 3; n2++) {
                const uint32_t ro = (uint32_t)(wn * 48 + n2 * 16) * 80 + ks * 32 + b_off;
                ldsm4(bb[n2], Bl + ro);
            }
            #pragma unroll
            for (int ma = 0; ma < 2; ma++)
                #pragma unroll
                for (int n2 = 0; n2 < 3; n2++) {
                    mma_bf16(acc[ma][2*n2],   ah[ma], bb[n2]);
                    mma_bf16(acc[ma][2*n2+1], ah[ma], bb[n2] + 2);
                }
        }

        if (more) { if (kh < 2) stsA(nbufb, vnext); CP_WAIT0(); }
        __syncthreads();
    }

    // ---- epilogue: smem transpose -> coalesced float4 stores ----
    {
        float* ys = (float*)smem;               // [144 co][128 px]
        const int t4 = lane >> 2, tp = (lane & 3) * 2;
        #pragma unroll
        for (int ma = 0; ma < 2; ma++) {
            const int r = wm * 32 + ma * 16 + t4;
            #pragma unroll
            for (int na = 0; na < 6; na++) {
                const int lc = wn * 48 + na * 8 + tp;
                ys[(size_t)lc * 128 + r]            = acc[ma][na][0];
                ys[(size_t)(lc + 1) * 128 + r]      = acc[ma][na][1];
                ys[(size_t)lc * 128 + r + 8]        = acc[ma][na][2];
                ys[(size_t)(lc + 1) * 128 + r + 8]  = acc[ma][na][3];
            }
        }
        __syncthreads();
        const int bt = (blockIdx.x * MT) / HW;
        const int q0 = blockIdx.x * MT - bt * HW;
        float* mb = msk + (size_t)bt * 144 * HW + q0;
        #pragma unroll
        for (int i = 0; i < 12; i++) {
            const int idx = t + i * 384;        // co*32 + p4
            const int co = idx >> 5, p4 = idx & 31;
            *(float4*)(mb + (size_t)co * HW + p4 * 4) = *(float4*)&ys[(size_t)co * 128 + p4 * 4];
        }
    }
}

// ---------------------------------------------------------------------------
// Kernel 3: softmax over 9 taps + unfold-weighted sum (gwc), logits from msk.
// ---------------------------------------------------------------------------
__global__ void __launch_bounds__(192)
softmax_unfold_gwc(const float* __restrict__ msk, const float* __restrict__ x,
                   float* __restrict__ out)
{
    using namespace cfg;
    const int ho  = blockIdx.y;
    const int b   = blockIdx.z;
    const int tid = threadIdx.x;
    const int q   = tid % 12;
    const int g   = tid / 12;
    const int px0 = blockIdx.x * 48 + q * 4;

    float lg[9][4];
    const float* mb = msk + ((size_t)(b * 144 + g * 9) * HOo + ho) * WOo + px0;
    #pragma unroll
    for (int j = 0; j < 9; j++) {
        float4 v = *(const float4*)(mb + (size_t)j * HW);
        lg[j][0] = v.x; lg[j][1] = v.y; lg[j][2] = v.z; lg[j][3] = v.w;
    }

    #pragma unroll
    for (int p = 0; p < 4; p++) {
        float mx = lg[0][p];
        #pragma unroll
        for (int j = 1; j < 9; j++) mx = fmaxf(mx, lg[j][p]);
        float s = 0.f;
        #pragma unroll
        for (int j = 0; j < 9; j++) { float e = expf(lg[j][p] - mx); lg[j][p] = e; s += e; }
        const float inv = 1.f / s;
        #pragma unroll
        for (int j = 0; j < 9; j++) lg[j][p] *= inv;
    }

    #pragma unroll
    for (int io = 0; io < 6; io++) {
        const int ch = io * 16 + g;
        const float* xc = x + (size_t)(b * G_CI + ch) * HWin;
        float o[4] = {0.f, 0.f, 0.f, 0.f};
        #pragma unroll
        for (int dy = 0; dy < 3; dy++) {
            const int h2 = 2 * ho + dy - 1;
            if ((unsigned)h2 < (unsigned)Hn) {
                const float* xr = xc + (size_t)h2 * Wn;
                const int wb = 2 * px0 - 1;
                float xv[9];
                #pragma unroll
                for (int k = 0; k < 9; k++) {
                    const int wi = wb + k;
                    xv[k] = ((unsigned)wi < (unsigned)Wn) ? xr[wi] : 0.f;
                }
                #pragma unroll
                for (int p = 0; p < 4; p++)
                    #pragma unroll
                    for (int dx = 0; dx < 3; dx++)
                        o[p] = fmaf(lg[dy * 3 + dx][p], xv[2 * p + dx], o[p]);
            }
        }
        *(float4*)(out + ((size_t)(b * G_CI + ch) * HOo + ho) * WOo + px0) =
            make_float4(o[0], o[1], o[2], o[3]);
    }
}

// ---------------------------------------------------------------------------
// Kernel 4: cat conv 3x3 s2 p1 (12->24) + BN + leakyReLU, direct per-pixel.
// 2 threads per output pixel (12 co each) for 2x occupancy: block handles
// 128 pixels; tid>>7 selects the channel half.
// ---------------------------------------------------------------------------
__global__ void __launch_bounds__(256)
conv_cat_direct(const float* __restrict__ x, const float* __restrict__ wgt,
                const float* __restrict__ bng, const float* __restrict__ bnb,
                const float* __restrict__ bnm, const float* __restrict__ bnv,
                float* __restrict__ y)
{
    using namespace cfg;
    __shared__ float ws[12 * 9 * 24];     // [ci][tap][co]
    __shared__ float sc_s[24], bi_s[24];

    const int tid = threadIdx.x;
    for (int i = tid; i < 2592; i += 256) {
        const int co = i % 24, tap = (i / 24) % 9, ci = i / 216;
        ws[i] = wgt[((size_t)co * 12 + ci) * 9 + tap];
    }
    if (tid < 24) {
        const float sc = bng[tid] * rsqrtf(bnv[tid] + 1e-5f);
        sc_s[tid] = sc;
        bi_s[tid] = bnb[tid] - bnm[tid] * sc;
    }
    __syncthreads();

    const int half = tid >> 7;                  // 0 or 1: channels half*12..
    const int p  = blockIdx.x * 128 + (tid & 127);
    const int b  = p / HW;
    const int q  = p - b * HW;
    const int ho = q / WOo, wo = q - ho * WOo;
    const float* xb = x + (size_t)b * 12 * HWin;
    const int co0 = half * 12;

    float acc[12];
    #pragma unroll
    for (int co = 0; co < 12; co++) acc[co] = 0.f;

    for (int ci = 0; ci < 12; ci++) {
        const float* xc = xb + (size_t)ci * HWin;
        float xv[9];
        #pragma unroll
        for (int dy = 0; dy < 3; dy++) {
            const int h2 = 2 * ho - 1 + dy;
            const bool vr = (unsigned)h2 < (unsigned)Hn;
            const float* xr = xc + (size_t)h2 * Wn;
            #pragma unroll
            for (int dx = 0; dx < 3; dx++) {
                const int w2 = 2 * wo - 1 + dx;
                xv[dy * 3 + dx] = (vr && (unsigned)w2 < (unsigned)Wn) ? xr[w2] : 0.f;
            }
        }
        #pragma unroll
        for (int tap = 0; tap < 9; tap++) {
            const float xt = xv[tap];
            const float4* wv = (const float4*)&ws[(ci * 9 + tap) * 24 + co0];
            #pragma unroll
            for (int c4 = 0; c4 < 3; c4++) {
                const float4 w4 = wv[c4];
                acc[c4 * 4 + 0] = fmaf(xt, w4.x, acc[c4 * 4 + 0]);
                acc[c4 * 4 + 1] = fmaf(xt, w4.y, acc[c4 * 4 + 1]);
                acc[c4 * 4 + 2] = fmaf(xt, w4.z, acc[c4 * 4 + 2]);
                acc[c4 * 4 + 3] = fmaf(xt, w4.w, acc[c4 * 4 + 3]);
            }
        }
    }

    float* yb = y + (size_t)b * 24 * HW + q;
    #pragma unroll
    for (int co = 0; co < 12; co++) {
        const int c = co0 + co;
        float v = fmaf(acc[co], sc_s[c], bi_s[c]);
        v = (v >= 0.f) ? v : 0.1f * v;
        yb[(size_t)c * HW] = v;
    }
}

// ---------------------------------------------------------------------------
// Fused 1x1 conv -> softmax(9) -> unfold (cat path, CIY=24 — small, L1-served)
// ---------------------------------------------------------------------------
template<int CI_X, int CIY, int G, int CPG, int QUADS>
__global__ void __launch_bounds__(G * QUADS)
mask_softmax_unfold(const float* __restrict__ y, const float* __restrict__ w2,
                    const float* __restrict__ x, float* __restrict__ out)
{
    using namespace cfg;
    const int wo0 = blockIdx.x * (QUADS * 4);
    const int ho  = blockIdx.y;
    const int b   = blockIdx.z;
    const int tid = threadIdx.x;
    const int q   = tid % QUADS;
    const int g   = tid / QUADS;
    const int px0 = wo0 + q * 4;

    float lg[9][4];
    #pragma unroll
    for (int j = 0; j < 9; j++)
        #pragma unroll
        for (int p = 0; p < 4; p++) lg[j][p] = 0.f;

    const size_t ybase = (size_t)b * CIY * HW + (size_t)ho * WOo + px0;
    const float* wg = w2 + (size_t)g * 9 * CIY;

    for (int c4 = 0; c4 < CIY; c4 += 4) {
        float4 yv0 = *(const float4*)(y + ybase + (size_t)(c4 + 0) * HW);
        float4 yv1 = *(const float4*)(y + ybase + (size_t)(c4 + 1) * HW);
        float4 yv2 = *(const float4*)(y + ybase + (size_t)(c4 + 2) * HW);
        float4 yv3 = *(const float4*)(y + ybase + (size_t)(c4 + 3) * HW);
        #pragma unroll
        for (int j = 0; j < 9; j++) {
            float4 wv = *(const float4*)(wg + j * CIY + c4);
            lg[j][0] += wv.x * yv0.x + wv.y * yv1.x + wv.z * yv2.x + wv.w * yv3.x;
            lg[j][1] += wv.x * yv0.y + wv.y * yv1.y + wv.z * yv2.y + wv.w * yv3.y;
            lg[j][2] += wv.x * yv0.z + wv.y * yv1.z + wv.z * yv2.z + wv.w * yv3.z;
            lg[j][3] += wv.x * yv0.w + wv.y * yv1.w + wv.z * yv2.w + wv.w * yv3.w;
        }
    }

    #pragma unroll
    for (int p = 0; p < 4; p++) {
        float mx = lg[0][p];
        #pragma unroll
        for (int j = 1; j < 9; j++) mx = fmaxf(mx, lg[j][p]);
        float s = 0.f;
        #pragma unroll
        for (int j = 0; j < 9; j++) { float e = expf(lg[j][p] - mx); lg[j][p] = e; s += e; }
        const float inv = 1.f / s;
        #pragma unroll
        for (int j = 0; j < 9; j++) lg[j][p] *= inv;
    }

    #pragma unroll
    for (int io = 0; io < CPG; io++) {
        const int ch = io * G + g;
        const float* xc = x + (size_t)(b * CI_X + ch) * Hn * Wn;
        float o[4] = {0.f, 0.f, 0.f, 0.f};
        #pragma unroll
        for (int dy = 0; dy < 3; dy++) {
            const int h2 = 2 * ho + dy - 1;
            if ((unsigned)h2 < (unsigned)Hn) {
                const float* xr = xc + (size_t)h2 * Wn;
                const int wb = 2 * px0 - 1;
                float xv[9];
                #pragma unroll
                for (int k = 0; k < 9; k++) {
                    const int wi = wb + k;
                    xv[k] = ((unsigned)wi < (unsigned)Wn) ? xr[wi] : 0.f;
                }
                #pragma unroll
                for (int p = 0; p < 4; p++)
                    #pragma unroll
                    for (int dx = 0; dx < 3; dx++)
                        o[p] = fmaf(lg[dy * 3 + dx][p], xv[2 * p + dx], o[p]);
            }
        }
        *(float4*)(out + ((size_t)(b * CI_X + ch) * HOo + ho) * WOo + px0) =
            make_float4(o[0], o[1], o[2], o[3]);
    }
}

// ---------------------------------------------------------------------------
// Cost volumes
// ---------------------------------------------------------------------------
__global__ void __launch_bounds__(288)
gwc_volume_kernel(const float* __restrict__ g8x, float* __restrict__ out)
{
    using namespace cfg;
    __shared__ float rs[2][12][WOo];
    const int h  = blockIdx.x * 2 + threadIdx.y;
    const int g  = blockIdx.y;
    const int b  = blockIdx.z;
    const int w  = threadIdx.x;
    const int hy = threadIdx.y;

    const float* rbase = g8x + ((size_t)((b + 2) * G_CI + g * 12) * HOo + h) * WOo;
    #pragma unroll
    for (int c = 0; c < 12; c++)
        rs[hy][c][w] = rbase[(size_t)c * HW + w];
    __syncthreads();

    const float* lbase = g8x + ((size_t)(b * G_CI + g * 12) * HOo + h) * WOo + w;
    float lr[12];
    #pragma unroll
    for (int c = 0; c < 12; c++) lr[c] = lbase[(size_t)c * HW];

    for (int d = 0; d < Dd; d++) {
        float s = 0.f;
        if (w >= d) {
            #pragma unroll
            for (int c = 0; c < 12; c++) s = fmaf(lr[c], rs[hy][c][w - d], s);
            s *= (1.f / 12.f);
        }
        out[(((size_t)(b * 32 + g) * Dd + d) * HOo + h) * WOo + w] = s;
    }
}

__global__ void cat_volume_kernel(const float* __restrict__ c8x, float* __restrict__ out)
{
    using namespace cfg;
    const int idx = blockIdx.x * blockDim.x + threadIdx.x;
    constexpr int TOT = 2 * 24 * Dd * HW;
    if (idx >= TOT) return;
    int t = idx;
    const int w = t % WOo;  t /= WOo;
    const int h = t % HOo;  t /= HOo;
    const int d = t % Dd;   t /= Dd;
    const int cc = t % 24;
    const int b  = t / 24;

    float v = 0.f;
    if (w >= d) {
        if (cc < 12)
            v = c8x[((size_t)(b * 12 + cc) * HOo + h) * WOo + w];
        else
            v = c8x[((size_t)((b + 2) * 12 + (cc - 12)) * HOo + h) * WOo + (w - d)];
    }
    out[(((size_t)(b * 32 + 8 + cc) * Dd + d) * HOo + h) * WOo + w] = v;
}

// ---------------------------------------------------------------------------
// Launch
// ---------------------------------------------------------------------------
extern "C" void kernel_launch(void* const* d_in, const int* in_sizes, int n_in,
                              void* d_out, int out_size)
{
    const float* gx  = (const float*)d_in[0];
    const float* cx  = (const float*)d_in[1];
    const float* gw1 = (const float*)d_in[2];
    const float* gbg = (const float*)d_in[3];
    const float* gbb = (const float*)d_in[4];
    const float* gbm = (const float*)d_in[5];
    const float* gbv = (const float*)d_in[6];
    const float* gw2 = (const float*)d_in[7];
    const float* cw1 = (const float*)d_in[8];
    const float* cbg = (const float*)d_in[9];
    const float* cbb = (const float*)d_in[10];
    const float* cbm = (const float*)d_in[11];
    const float* cbv = (const float*)d_in[12];
    const float* cw2 = (const float*)d_in[13];
    float* out = (float*)d_out;

    float *y1, *g8x, *y2, *c8x, *msk;
    cudaGetSymbolAddress((void**)&y1,  d_y1);
    cudaGetSymbolAddress((void**)&g8x, d_g8x);
    cudaGetSymbolAddress((void**)&y2,  d_y2);
    cudaGetSymbolAddress((void**)&c8x, d_c8x);
    cudaGetSymbolAddress((void**)&msk, d_msk);

    cudaFuncSetAttribute(conv_gwc_mma, cudaFuncAttributeMaxDynamicSharedMemorySize, SM_CONV);
    cudaFuncSetAttribute(gemm_logits_mma, cudaFuncAttributeMaxDynamicSharedMemorySize, SM_LOG);

    wprep_kernel<<<(cfg::NCHUNK * 192 * 32 + 255) / 256, 256>>>(gw1);
    wprep2_kernel<<<(6 * 144 * 32 + 255) / 256, 256>>>(gw2);

    conv_gwc_mma<<<360, 512, SM_CONV>>>(gx, gbg, gbb, gbm, gbv, y1);

    conv_cat_direct<<<(cfg::B * cfg::HW) / 128, 256>>>(
        cx, cw1, cbg, cbb, cbm, cbv, y2);

    gemm_logits_mma<<<360, 384, SM_LOG>>>(y1, msk);
    softmax_unfold_gwc<<<dim3(3, 80, 4), 192>>>(msk, gx, g8x);

    mask_softmax_unfold<12, 24, 12, 1, 12><<<dim3(3, 80, 4), 144>>>(y2, cw2, cx, c8x);

    gwc_volume_kernel<<<dim3(40, 8, 2), dim3(144, 2)>>>(g8x, out);
    cat_volume_kernel<<<(2 * 24 * cfg::Dd * cfg::HW + 255) / 256, 256>>>(c8x, out);
}

// round 10
// speedup vs baseline: 1.1551x; 1.1551x over previous
#include <cuda_runtime.h>
#include <cuda_bf16.h>
#include <cstdint>
#include <cstddef>

// ---------------------------------------------------------------------------
// Problem constants
// ---------------------------------------------------------------------------
namespace cfg {
constexpr int B   = 4;
constexpr int Hn  = 160, Wn = 288;      // input H, W
constexpr int HOo = 80,  WOo = 144;     // output H, W (stride 2)
constexpr int HW  = HOo * WOo;          // 11520
constexpr int HWin = Hn * Wn;           // 46080
constexpr int Dd  = 24;                 // disparity levels
constexpr int G_CI = 96, G_CO = 192;
constexpr int NCHUNK = 27;              // conv: 27 chunks of 32 k (tap-major)
constexpr int MT = 128;                 // pixels per CTA
}

// Scratch (static device globals — no allocation allowed)
__device__ float d_y1 [(size_t)cfg::B * cfg::G_CO * cfg::HW];   // 35.4 MB
__device__ float d_g8x[(size_t)cfg::B * cfg::G_CI * cfg::HW];   // 17.7 MB
__device__ float d_y2 [(size_t)cfg::B * 24 * cfg::HW];          //  4.4 MB
__device__ float d_c8x[(size_t)cfg::B * 12 * cfg::HW];          //  2.2 MB
__device__ float d_msk[(size_t)cfg::B * 144 * cfg::HW];         // 26.5 MB (gwc logits)
// Pre-split bf16 conv weights: [chunk 27][nhalf 2] blobs of 15360B
__device__ uint4 d_wB[(size_t)cfg::NCHUNK * 2 * 960];
// Pre-split bf16 mask weights: [chunk 6] blobs of 23040B (hi 144x40 | lo 144x40)
__device__ uint4 d_wM[(size_t)6 * 1440];

// ---------------------------------------------------------------------------
// PTX helpers (sm_80-compatible only: ldmatrix / mma.sync / cp.async)
// ---------------------------------------------------------------------------
__device__ __forceinline__ uint32_t smem_u32(const void* p) {
    uint32_t a;
    asm("{ .reg .u64 t; cvta.to.shared.u64 t, %1; cvt.u32.u64 %0, t; }" : "=r"(a) : "l"(p));
    return a;
}
__device__ __forceinline__ void ldsm4(uint32_t* r, uint32_t addr) {
    asm volatile("ldmatrix.sync.aligned.m8n8.x4.shared.b16 {%0,%1,%2,%3}, [%4];"
        : "=r"(r[0]), "=r"(r[1]), "=r"(r[2]), "=r"(r[3]) : "r"(addr));
}
__device__ __forceinline__ void mma_bf16(float* c, const uint32_t* a, const uint32_t* b) {
    asm volatile(
        "mma.sync.aligned.m16n8k16.row.col.f32.bf16.bf16.f32 "
        "{%0,%1,%2,%3}, {%4,%5,%6,%7}, {%8,%9}, {%0,%1,%2,%3};"
        : "+f"(c[0]), "+f"(c[1]), "+f"(c[2]), "+f"(c[3])
        : "r"(a[0]), "r"(a[1]), "r"(a[2]), "r"(a[3]), "r"(b[0]), "r"(b[1]));
}
#define CP_ASYNC16(dst, src) \
    asm volatile("cp.async.cg.shared.global [%0], [%1], 16;" :: "r"(dst), "l"(src) : "memory")
#define CP_COMMIT()  asm volatile("cp.async.commit_group;" ::: "memory")
#define CP_WAIT0()   asm volatile("cp.async.wait_group 0;" ::: "memory")

__device__ __forceinline__ void bf16_split(float v, uint16_t& h, uint16_t& l) {
    __nv_bfloat16 hb = __float2bfloat16_rn(v);
    __nv_bfloat16 lb = __float2bfloat16_rn(v - __bfloat162float(hb));
    h = __bfloat16_as_ushort(hb);
    l = __bfloat16_as_ushort(lb);
}

// ---------------------------------------------------------------------------
// Kernel 0a: conv weight prep. chunk = tap*3 + ci/32; rows padded to 40 bf16.
// blob = [hi 96x40 | lo 96x40] per (chunk, co-half).
// ---------------------------------------------------------------------------
__global__ void wprep_kernel(const float* __restrict__ w) {
    using namespace cfg;
    int idx = blockIdx.x * blockDim.x + threadIdx.x;
    if (idx >= NCHUNK * 192 * 32) return;
    int k = idx & 31, co = (idx >> 5) % 192, c = idx / (32 * 192);
    int tap = c / 3, ci = (c % 3) * 32 + k;
    float v = w[(size_t)(co * G_CI + ci) * 9 + tap];
    uint16_t hi, lo; bf16_split(v, hi, lo);
    uint16_t* blob = (uint16_t*)d_wB + (size_t)(c * 2 + co / 96) * 7680;
    int col = co % 96;
    blob[col * 40 + k]        = hi;
    blob[3840 + col * 40 + k] = lo;
}

// ---------------------------------------------------------------------------
// Kernel 0b: gwc mask (1x1) weight prep. 6 chunks of 32 k; rows 40 bf16.
// ---------------------------------------------------------------------------
__global__ void wprep2_kernel(const float* __restrict__ w2) {
    using namespace cfg;
    int idx = blockIdx.x * blockDim.x + threadIdx.x;
    if (idx >= 6 * 144 * 32) return;
    int k = idx & 31, co = (idx >> 5) % 144, c = idx / (32 * 144);
    int ci = c * 32 + k;
    float v = w2[(size_t)co * 192 + ci];
    uint16_t hi, lo; bf16_split(v, hi, lo);
    uint16_t* blob = (uint16_t*)d_wM + (size_t)c * 11520;
    blob[co * 40 + k]        = hi;
    blob[5760 + co * 40 + k] = lo;
}

// ---------------------------------------------------------------------------
// Kernel 1: conv3x3 s2 p1 (96->192) + BN + leakyReLU, implicit GEMM,
// mma.sync bf16 hi/lo (3-pass). CTA: 128px x 96co, 8 warps (4Mx2N).
// (round-6 known-good shape: 2 CTAs/SM, blockIdx.y selects co-half)
// ---------------------------------------------------------------------------
static constexpr int BUF_STRIDE = 35840;
static constexpr int SM_BN      = 2 * BUF_STRIDE;         // 71680
static constexpr int SM_CONV    = SM_BN + 768;            // 72448

__global__ void __launch_bounds__(256, 2)
conv_gwc_mma(const float* __restrict__ x,
             const float* __restrict__ bng, const float* __restrict__ bnb,
             const float* __restrict__ bnm, const float* __restrict__ bnv,
             float* __restrict__ y)
{
    using namespace cfg;
    extern __shared__ char smem[];
    const uint32_t sb = smem_u32(smem);
    const int t = threadIdx.x, lane = t & 31, wid = t >> 5;
    const int wm = wid & 3, wn = wid >> 2;

    float* sc_s = (float*)(smem + SM_BN);
    float* bi_s = (float*)(smem + SM_BN + 384);
    if (t < 96) {
        const int co = blockIdx.y * 96 + t;
        const float sc = bng[co] * rsqrtf(bnv[co] + 1e-5f);
        sc_s[t] = sc;
        bi_s[t] = bnb[co] - bnm[co] * sc;
    }

    const int pl = t & 127, khalf = t >> 7;
    const int p  = blockIdx.x * MT + pl;
    const int b  = p / HW;
    const int q  = p - b * HW;
    const int ho = q / WOo, wo = q - ho * WOo;
    const float* xb = x + (size_t)b * G_CI * HWin;

    const uint32_t a_off = (uint32_t)((lane & 7) + ((lane >> 3) & 1) * 8) * 80
                         + ((lane >> 4) << 4);
    const uint32_t b_off = (uint32_t)(((lane >> 4) * 8) + (lane & 7)) * 80
                         + (((lane >> 3) & 1) << 4);

    float acc[2][6][4];
    #pragma unroll
    for (int i = 0; i < 2; i++)
        #pragma unroll
        for (int j = 0; j < 6; j++)
            #pragma unroll
            for (int r = 0; r < 4; r++) acc[i][j][r] = 0.f;

    auto ldgA = [&](int c, float* v) {
        const int tap = c / 3, dy = tap / 3, dx = tap - dy * 3;
        const int ci0 = (c - tap * 3) * 32 + khalf * 16;
        const int h2 = 2 * ho - 1 + dy, w2 = 2 * wo - 1 + dx;
        const bool vr = ((unsigned)h2 < (unsigned)Hn) && ((unsigned)w2 < (unsigned)Wn);
        const float* xp = xb + (size_t)h2 * Wn + w2 + (size_t)ci0 * HWin;
        #pragma unroll
        for (int i = 0; i < 16; i++) v[i] = vr ? xp[(size_t)i * HWin] : 0.f;
    };
    auto stsA = [&](uint32_t bufb, const float* v) {
        uint32_t hp[8], lp[8];
        #pragma unroll
        for (int i = 0; i < 8; i++) {
            uint16_t h0, l0, h1, l1;
            bf16_split(v[2*i], h0, l0);
            bf16_split(v[2*i+1], h1, l1);
            hp[i] = (uint32_t)h0 | ((uint32_t)h1 << 16);
            lp[i] = (uint32_t)l0 | ((uint32_t)l1 << 16);
        }
        const uint32_t off = (uint32_t)pl * 80 + khalf * 32;
        *(uint4*)(smem + bufb + off)           = make_uint4(hp[0], hp[1], hp[2], hp[3]);
        *(uint4*)(smem + bufb + off + 16)      = make_uint4(hp[4], hp[5], hp[6], hp[7]);
        *(uint4*)(smem + bufb + 10240 + off)      = make_uint4(lp[0], lp[1], lp[2], lp[3]);
        *(uint4*)(smem + bufb + 10240 + off + 16) = make_uint4(lp[4], lp[5], lp[6], lp[7]);
    };
    auto cpB = [&](int c, uint32_t bufb) {
        const char* src = (const char*)d_wB + (size_t)(c * 2 + blockIdx.y) * 15360;
        const uint32_t dst = sb + bufb + 20480;
        #pragma unroll
        for (int j = t; j < 960; j += 256)
            CP_ASYNC16(dst + j * 16, src + (size_t)j * 16);
        CP_COMMIT();
    };

    {
        cpB(0, 0);
        float v0[16];
        ldgA(0, v0);
        stsA(0, v0);
        CP_WAIT0();
    }
    __syncthreads();

    float vnext[16];
    for (int c = 0; c < NCHUNK; c++) {
        const uint32_t bufb  = (uint32_t)(c & 1) * BUF_STRIDE;
        const uint32_t nbufb = (uint32_t)((c + 1) & 1) * BUF_STRIDE;
        const bool more = (c + 1 < NCHUNK);
        if (more) { cpB(c + 1, nbufb); ldgA(c + 1, vnext); }

        const uint32_t Ah = sb + bufb, Al = Ah + 10240;
        const uint32_t Bh = sb + bufb + 20480, Bl = Bh + 7680;
        #pragma unroll
        for (int ks = 0; ks < 2; ks++) {
            uint32_t ah[2][4], al[2][4], bb[3][4];
            #pragma unroll
            for (int ma = 0; ma < 2; ma++) {
                const uint32_t ro = (uint32_t)(wm * 32 + ma * 16) * 80 + ks * 32 + a_off;
                ldsm4(ah[ma], Ah + ro);
                ldsm4(al[ma], Al + ro);
            }
            #pragma unroll
            for (int n2 = 0; n2 < 3; n2++) {
                const uint32_t ro = (uint32_t)(wn * 48 + n2 * 16) * 80 + ks * 32 + b_off;
                ldsm4(bb[n2], Bh + ro);
            }
            #pragma unroll
            for (int ma = 0; ma < 2; ma++)
                #pragma unroll
                for (int n2 = 0; n2 < 3; n2++) {
                    mma_bf16(acc[ma][2*n2],   ah[ma], bb[n2]);
                    mma_bf16(acc[ma][2*n2+1], ah[ma], bb[n2] + 2);
                    mma_bf16(acc[ma][2*n2],   al[ma], bb[n2]);
                    mma_bf16(acc[ma][2*n2+1], al[ma], bb[n2] + 2);
                }
            #pragma unroll
            for (int n2 = 0; n2 < 3; n2++) {
                const uint32_t ro = (uint32_t)(wn * 48 + n2 * 16) * 80 + ks * 32 + b_off;
                ldsm4(bb[n2], Bl + ro);
            }
            #pragma unroll
            for (int ma = 0; ma < 2; ma++)
                #pragma unroll
                for (int n2 = 0; n2 < 3; n2++) {
                    mma_bf16(acc[ma][2*n2],   ah[ma], bb[n2]);
                    mma_bf16(acc[ma][2*n2+1], ah[ma], bb[n2] + 2);
                }
        }

        if (more) { stsA(nbufb, vnext); CP_WAIT0(); }
        __syncthreads();
    }

    // ---- epilogue: BN + leaky relu, scalar stores ----
    {
        const int bt = (blockIdx.x * MT) / HW;          // tile never straddles b
        const int q0 = blockIdx.x * MT - bt * HW;
        float* yb = y + (size_t)bt * G_CO * HW + q0;
        const int t4 = lane >> 2, tp = (lane & 3) * 2;
        #pragma unroll
        for (int ma = 0; ma < 2; ma++) {
            const int r = wm * 32 + ma * 16 + t4;
            #pragma unroll
            for (int na = 0; na < 6; na++) {
                const int lc = wn * 48 + na * 8 + tp;
                const int co = blockIdx.y * 96 + lc;
                const float s0 = sc_s[lc], b0 = bi_s[lc];
                const float s1 = sc_s[lc + 1], b1 = bi_s[lc + 1];
                float v00 = fmaf(acc[ma][na][0], s0, b0);
                float v01 = fmaf(acc[ma][na][1], s1, b1);
                float v10 = fmaf(acc[ma][na][2], s0, b0);
                float v11 = fmaf(acc[ma][na][3], s1, b1);
                v00 = (v00 >= 0.f) ? v00 : 0.1f * v00;
                v01 = (v01 >= 0.f) ? v01 : 0.1f * v01;
                v10 = (v10 >= 0.f) ? v10 : 0.1f * v10;
                v11 = (v11 >= 0.f) ? v11 : 0.1f * v11;
                yb[(size_t)co * HW + r]           = v00;
                yb[(size_t)(co + 1) * HW + r]     = v01;
                yb[(size_t)co * HW + r + 8]       = v10;
                yb[(size_t)(co + 1) * HW + r + 8] = v11;
            }
        }
    }
}

// ---------------------------------------------------------------------------
// Kernel 2: gwc mask logits GEMM: msk[144, px] = w2[144,192] . y1[192, px].
// CTA: 128 px x 144 co, 12 warps (4M x 3N), warp tile 32x48.
// ---------------------------------------------------------------------------
static constexpr int LBUF   = 43520;
static constexpr int SM_LOG = 2 * LBUF;                   // 87040

__global__ void __launch_bounds__(384, 1)
gemm_logits_mma(const float* __restrict__ y, float* __restrict__ msk)
{
    using namespace cfg;
    extern __shared__ char smem[];
    const uint32_t sb = smem_u32(smem);
    const int t = threadIdx.x, lane = t & 31, wid = t >> 5;
    const int wm = wid & 3, wn = wid >> 2;        // wn 0..2

    const int pl = t & 127, kh = t >> 7;          // kh 0..2; only kh<2 stage A
    const int p  = blockIdx.x * MT + pl;
    const int b  = p / HW;
    const int q  = p - b * HW;
    const float* yb = y + (size_t)b * G_CO * HW + q;

    const uint32_t a_off = (uint32_t)((lane & 7) + ((lane >> 3) & 1) * 8) * 80
                         + ((lane >> 4) << 4);
    const uint32_t b_off = (uint32_t)(((lane >> 4) * 8) + (lane & 7)) * 80
                         + (((lane >> 3) & 1) << 4);

    float acc[2][6][4];
    #pragma unroll
    for (int i = 0; i < 2; i++)
        #pragma unroll
        for (int j = 0; j < 6; j++)
            #pragma unroll
            for (int r = 0; r < 4; r++) acc[i][j][r] = 0.f;

    auto ldgA = [&](int c, float* v) {
        const float* yp = yb + (size_t)(c * 32 + kh * 16) * HW;
        #pragma unroll
        for (int i = 0; i < 16; i++) v[i] = yp[(size_t)i * HW];
    };
    auto stsA = [&](uint32_t bufb, const float* v) {
        uint32_t hp[8], lp[8];
        #pragma unroll
        for (int i = 0; i < 8; i++) {
            uint16_t h0, l0, h1, l1;
            bf16_split(v[2*i], h0, l0);
            bf16_split(v[2*i+1], h1, l1);
            hp[i] = (uint32_t)h0 | ((uint32_t)h1 << 16);
            lp[i] = (uint32_t)l0 | ((uint32_t)l1 << 16);
        }
        const uint32_t off = (uint32_t)pl * 80 + kh * 32;
        *(uint4*)(smem + bufb + off)           = make_uint4(hp[0], hp[1], hp[2], hp[3]);
        *(uint4*)(smem + bufb + off + 16)      = make_uint4(hp[4], hp[5], hp[6], hp[7]);
        *(uint4*)(smem + bufb + 10240 + off)      = make_uint4(lp[0], lp[1], lp[2], lp[3]);
        *(uint4*)(smem + bufb + 10240 + off + 16) = make_uint4(lp[4], lp[5], lp[6], lp[7]);
    };
    auto cpB = [&](int c, uint32_t bufb) {
        const char* src = (const char*)d_wM + (size_t)c * 23040;
        const uint32_t dst = sb + bufb + 20480;
        for (int j = t; j < 1440; j += 384)
            CP_ASYNC16(dst + j * 16, src + (size_t)j * 16);
        CP_COMMIT();
    };

    {
        cpB(0, 0);
        if (kh < 2) {
            float v0[16];
            ldgA(0, v0);
            stsA(0, v0);
        }
        CP_WAIT0();
    }
    __syncthreads();

    float vnext[16];
    for (int c = 0; c < 6; c++) {
        const uint32_t bufb  = (uint32_t)(c & 1) * LBUF;
        const uint32_t nbufb = (uint32_t)((c + 1) & 1) * LBUF;
        const bool more = (c + 1 < 6);
        if (more) { cpB(c + 1, nbufb); if (kh < 2) ldgA(c + 1, vnext); }

        const uint32_t Ah = sb + bufb, Al = Ah + 10240;
        const uint32_t Bh = sb + bufb + 20480, Bl = Bh + 11520;
        #pragma unroll
        for (int ks = 0; ks < 2; ks++) {
            uint32_t ah[2][4], al[2][4], bb[3][4];
            #pragma unroll
            for (int ma = 0; ma < 2; ma++) {
                const uint32_t ro = (uint32_t)(wm * 32 + ma * 16) * 80 + ks * 32 + a_off;
                ldsm4(ah[ma], Ah + ro);
                ldsm4(al[ma], Al + ro);
            }
            #pragma unroll
            for (int n2 = 0; n2 < 3; n2++) {
                const uint32_t ro = (uint32_t)(wn * 48 + n2 * 16) * 80 + ks * 32 + b_off;
                ldsm4(bb[n2], Bh + ro);
            }
            #pragma unroll
            for (int ma = 0; ma < 2; ma++)
                #pragma unroll
                for (int n2 = 0; n2 < 3; n2++) {
                    mma_bf16(acc[ma][2*n2],   ah[ma], bb[n2]);
                    mma_bf16(acc[ma][2*n2+1], ah[ma], bb[n2] + 2);
                    mma_bf16(acc[ma][2*n2],   al[ma], bb[n2]);
                    mma_bf16(acc[ma][2*n2+1], al[ma], bb[n2] + 2);
                }
            #pragma unroll
            for (int n2 = 0; n2 < 3; n2++) {
                const uint32_t ro = (uint32_t)(wn * 48 + n2 * 16) * 80 + ks * 32 + b_off;
                ldsm4(bb[n2], Bl + ro);
            }
            #pragma unroll
            for (int ma = 0; ma < 2; ma++)
                #pragma unroll
                for (int n2 = 0; n2 < 3; n2++) {
                    mma_bf16(acc[ma][2*n2],   ah[ma], bb[n2]);
                    mma_bf16(acc[ma][2*n2+1], ah[ma], bb[n2] + 2);
                }
        }

        if (more) { if (kh < 2) stsA(nbufb, vnext); CP_WAIT0(); }
        __syncthreads();
    }

    // ---- epilogue: smem transpose -> coalesced float4 stores ----
    {
        float* ys = (float*)smem;               // [144 co][128 px]
        const int t4 = lane >> 2, tp = (lane & 3) * 2;
        #pragma unroll
        for (int ma = 0; ma < 2; ma++) {
            const int r = wm * 32 + ma * 16 + t4;
            #pragma unroll
            for (int na = 0; na < 6; na++) {
                const int lc = wn * 48 + na * 8 + tp;
                ys[(size_t)lc * 128 + r]            = acc[ma][na][0];
                ys[(size_t)(lc + 1) * 128 + r]      = acc[ma][na][1];
                ys[(size_t)lc * 128 + r + 8]        = acc[ma][na][2];
                ys[(size_t)(lc + 1) * 128 + r + 8]  = acc[ma][na][3];
            }
        }
        __syncthreads();
        const int bt = (blockIdx.x * MT) / HW;
        const int q0 = blockIdx.x * MT - bt * HW;
        float* mb = msk + (size_t)bt * 144 * HW + q0;
        #pragma unroll
        for (int i = 0; i < 12; i++) {
            const int idx = t + i * 384;        // co*32 + p4
            const int co = idx >> 5, p4 = idx & 31;
            *(float4*)(mb + (size_t)co * HW + p4 * 4) = *(float4*)&ys[(size_t)co * 128 + p4 * 4];
        }
    }
}

// ---------------------------------------------------------------------------
// Kernel 3: softmax over 9 taps + unfold-weighted sum (gwc), logits from msk.
// ---------------------------------------------------------------------------
__global__ void __launch_bounds__(192)
softmax_unfold_gwc(const float* __restrict__ msk, const float* __restrict__ x,
                   float* __restrict__ out)
{
    using namespace cfg;
    const int ho  = blockIdx.y;
    const int b   = blockIdx.z;
    const int tid = threadIdx.x;
    const int q   = tid % 12;
    const int g   = tid / 12;
    const int px0 = blockIdx.x * 48 + q * 4;

    float lg[9][4];
    const float* mb = msk + ((size_t)(b * 144 + g * 9) * HOo + ho) * WOo + px0;
    #pragma unroll
    for (int j = 0; j < 9; j++) {
        float4 v = *(const float4*)(mb + (size_t)j * HW);
        lg[j][0] = v.x; lg[j][1] = v.y; lg[j][2] = v.z; lg[j][3] = v.w;
    }

    #pragma unroll
    for (int p = 0; p < 4; p++) {
        float mx = lg[0][p];
        #pragma unroll
        for (int j = 1; j < 9; j++) mx = fmaxf(mx, lg[j][p]);
        float s = 0.f;
        #pragma unroll
        for (int j = 0; j < 9; j++) { float e = expf(lg[j][p] - mx); lg[j][p] = e; s += e; }
        const float inv = 1.f / s;
        #pragma unroll
        for (int j = 0; j < 9; j++) lg[j][p] *= inv;
    }

    #pragma unroll
    for (int io = 0; io < 6; io++) {
        const int ch = io * 16 + g;
        const float* xc = x + (size_t)(b * G_CI + ch) * HWin;
        float o[4] = {0.f, 0.f, 0.f, 0.f};
        #pragma unroll
        for (int dy = 0; dy < 3; dy++) {
            const int h2 = 2 * ho + dy - 1;
            if ((unsigned)h2 < (unsigned)Hn) {
                const float* xr = xc + (size_t)h2 * Wn;
                const int wb = 2 * px0 - 1;
                float xv[9];
                #pragma unroll
                for (int k = 0; k < 9; k++) {
                    const int wi = wb + k;
                    xv[k] = ((unsigned)wi < (unsigned)Wn) ? xr[wi] : 0.f;
                }
                #pragma unroll
                for (int p = 0; p < 4; p++)
                    #pragma unroll
                    for (int dx = 0; dx < 3; dx++)
                        o[p] = fmaf(lg[dy * 3 + dx][p], xv[2 * p + dx], o[p]);
            }
        }
        *(float4*)(out + ((size_t)(b * G_CI + ch) * HOo + ho) * WOo + px0) =
            make_float4(o[0], o[1], o[2], o[3]);
    }
}

// ---------------------------------------------------------------------------
// Kernel 4: cat conv 3x3 s2 p1 (12->24) + BN + leakyReLU, direct per-pixel.
// 2 threads per output pixel (12 co each): block handles 128 pixels.
// ---------------------------------------------------------------------------
__global__ void __launch_bounds__(256)
conv_cat_direct(const float* __restrict__ x, const float* __restrict__ wgt,
                const float* __restrict__ bng, const float* __restrict__ bnb,
                const float* __restrict__ bnm, const float* __restrict__ bnv,
                float* __restrict__ y)
{
    using namespace cfg;
    __shared__ float ws[12 * 9 * 24];     // [ci][tap][co]
    __shared__ float sc_s[24], bi_s[24];

    const int tid = threadIdx.x;
    for (int i = tid; i < 2592; i += 256) {
        const int co = i % 24, tap = (i / 24) % 9, ci = i / 216;
        ws[i] = wgt[((size_t)co * 12 + ci) * 9 + tap];
    }
    if (tid < 24) {
        const float sc = bng[tid] * rsqrtf(bnv[tid] + 1e-5f);
        sc_s[tid] = sc;
        bi_s[tid] = bnb[tid] - bnm[tid] * sc;
    }
    __syncthreads();

    const int half = tid >> 7;                  // 0 or 1: channels half*12..
    const int p  = blockIdx.x * 128 + (tid & 127);
    const int b  = p / HW;
    const int q  = p - b * HW;
    const int ho = q / WOo, wo = q - ho * WOo;
    const float* xb = x + (size_t)b * 12 * HWin;
    const int co0 = half * 12;

    float acc[12];
    #pragma unroll
    for (int co = 0; co < 12; co++) acc[co] = 0.f;

    for (int ci = 0; ci < 12; ci++) {
        const float* xc = xb + (size_t)ci * HWin;
        float xv[9];
        #pragma unroll
        for (int dy = 0; dy < 3; dy++) {
            const int h2 = 2 * ho - 1 + dy;
            const bool vr = (unsigned)h2 < (unsigned)Hn;
            const float* xr = xc + (size_t)h2 * Wn;
            #pragma unroll
            for (int dx = 0; dx < 3; dx++) {
                const int w2 = 2 * wo - 1 + dx;
                xv[dy * 3 + dx] = (vr && (unsigned)w2 < (unsigned)Wn) ? xr[w2] : 0.f;
            }
        }
        #pragma unroll
        for (int tap = 0; tap < 9; tap++) {
            const float xt = xv[tap];
            const float4* wv = (const float4*)&ws[(ci * 9 + tap) * 24 + co0];
            #pragma unroll
            for (int c4 = 0; c4 < 3; c4++) {
                const float4 w4 = wv[c4];
                acc[c4 * 4 + 0] = fmaf(xt, w4.x, acc[c4 * 4 + 0]);
                acc[c4 * 4 + 1] = fmaf(xt, w4.y, acc[c4 * 4 + 1]);
                acc[c4 * 4 + 2] = fmaf(xt, w4.z, acc[c4 * 4 + 2]);
                acc[c4 * 4 + 3] = fmaf(xt, w4.w, acc[c4 * 4 + 3]);
            }
        }
    }

    float* yb = y + (size_t)b * 24 * HW + q;
    #pragma unroll
    for (int co = 0; co < 12; co++) {
        const int c = co0 + co;
        float v = fmaf(acc[co], sc_s[c], bi_s[c]);
        v = (v >= 0.f) ? v : 0.1f * v;
        yb[(size_t)c * HW] = v;
    }
}

// ---------------------------------------------------------------------------
// Fused 1x1 conv -> softmax(9) -> unfold (cat path, CIY=24 — small, L1-served)
// ---------------------------------------------------------------------------
template<int CI_X, int CIY, int G, int CPG, int QUADS>
__global__ void __launch_bounds__(G * QUADS)
mask_softmax_unfold(const float* __restrict__ y, const float* __restrict__ w2,
                    const float* __restrict__ x, float* __restrict__ out)
{
    using namespace cfg;
    const int wo0 = blockIdx.x * (QUADS * 4);
    const int ho  = blockIdx.y;
    const int b   = blockIdx.z;
    const int tid = threadIdx.x;
    const int q   = tid % QUADS;
    const int g   = tid / QUADS;
    const int px0 = wo0 + q * 4;

    float lg[9][4];
    #pragma unroll
    for (int j = 0; j < 9; j++)
        #pragma unroll
        for (int p = 0; p < 4; p++) lg[j][p] = 0.f;

    const size_t ybase = (size_t)b * CIY * HW + (size_t)ho * WOo + px0;
    const float* wg = w2 + (size_t)g * 9 * CIY;

    for (int c4 = 0; c4 < CIY; c4 += 4) {
        float4 yv0 = *(const float4*)(y + ybase + (size_t)(c4 + 0) * HW);
        float4 yv1 = *(const float4*)(y + ybase + (size_t)(c4 + 1) * HW);
        float4 yv2 = *(const float4*)(y + ybase + (size_t)(c4 + 2) * HW);
        float4 yv3 = *(const float4*)(y + ybase + (size_t)(c4 + 3) * HW);
        #pragma unroll
        for (int j = 0; j < 9; j++) {
            float4 wv = *(const float4*)(wg + j * CIY + c4);
            lg[j][0] += wv.x * yv0.x + wv.y * yv1.x + wv.z * yv2.x + wv.w * yv3.x;
            lg[j][1] += wv.x * yv0.y + wv.y * yv1.y + wv.z * yv2.y + wv.w * yv3.y;
            lg[j][2] += wv.x * yv0.z + wv.y * yv1.z + wv.z * yv2.z + wv.w * yv3.z;
            lg[j][3] += wv.x * yv0.w + wv.y * yv1.w + wv.z * yv2.w + wv.w * yv3.w;
        }
    }

    #pragma unroll
    for (int p = 0; p < 4; p++) {
        float mx = lg[0][p];
        #pragma unroll
        for (int j = 1; j < 9; j++) mx = fmaxf(mx, lg[j][p]);
        float s = 0.f;
        #pragma unroll
        for (int j = 0; j < 9; j++) { float e = expf(lg[j][p] - mx); lg[j][p] = e; s += e; }
        const float inv = 1.f / s;
        #pragma unroll
        for (int j = 0; j < 9; j++) lg[j][p] *= inv;
    }

    #pragma unroll
    for (int io = 0; io < CPG; io++) {
        const int ch = io * G + g;
        const float* xc = x + (size_t)(b * CI_X + ch) * Hn * Wn;
        float o[4] = {0.f, 0.f, 0.f, 0.f};
        #pragma unroll
        for (int dy = 0; dy < 3; dy++) {
            const int h2 = 2 * ho + dy - 1;
            if ((unsigned)h2 < (unsigned)Hn) {
                const float* xr = xc + (size_t)h2 * Wn;
                const int wb = 2 * px0 - 1;
                float xv[9];
                #pragma unroll
                for (int k = 0; k < 9; k++) {
                    const int wi = wb + k;
                    xv[k] = ((unsigned)wi < (unsigned)Wn) ? xr[wi] : 0.f;
                }
                #pragma unroll
                for (int p = 0; p < 4; p++)
                    #pragma unroll
                    for (int dx = 0; dx < 3; dx++)
                        o[p] = fmaf(lg[dy * 3 + dx][p], xv[2 * p + dx], o[p]);
            }
        }
        *(float4*)(out + ((size_t)(b * CI_X + ch) * HOo + ho) * WOo + px0) =
            make_float4(o[0], o[1], o[2], o[3]);
    }
}

// ---------------------------------------------------------------------------
// Cost volumes
// ---------------------------------------------------------------------------
__global__ void __launch_bounds__(288)
gwc_volume_kernel(const float* __restrict__ g8x, float* __restrict__ out)
{
    using namespace cfg;
    __shared__ float rs[2][12][WOo];
    const int h  = blockIdx.x * 2 + threadIdx.y;
    const int g  = blockIdx.y;
    const int b  = blockIdx.z;
    const int w  = threadIdx.x;
    const int hy = threadIdx.y;

    const float* rbase = g8x + ((size_t)((b + 2) * G_CI + g * 12) * HOo + h) * WOo;
    #pragma unroll
    for (int c = 0; c < 12; c++)
        rs[hy][c][w] = rbase[(size_t)c * HW + w];
    __syncthreads();

    const float* lbase = g8x + ((size_t)(b * G_CI + g * 12) * HOo + h) * WOo + w;
    float lr[12];
    #pragma unroll
    for (int c = 0; c < 12; c++) lr[c] = lbase[(size_t)c * HW];

    for (int d = 0; d < Dd; d++) {
        float s = 0.f;
        if (w >= d) {
            #pragma unroll
            for (int c = 0; c < 12; c++) s = fmaf(lr[c], rs[hy][c][w - d], s);
            s *= (1.f / 12.f);
        }
        out[(((size_t)(b * 32 + g) * Dd + d) * HOo + h) * WOo + w] = s;
    }
}

__global__ void cat_volume_kernel(const float* __restrict__ c8x, float* __restrict__ out)
{
    using namespace cfg;
    const int idx = blockIdx.x * blockDim.x + threadIdx.x;
    constexpr int TOT = 2 * 24 * Dd * HW;
    if (idx >= TOT) return;
    int t = idx;
    const int w = t % WOo;  t /= WOo;
    const int h = t % HOo;  t /= HOo;
    const int d = t % Dd;   t /= Dd;
    const int cc = t % 24;
    const int b  = t / 24;

    float v = 0.f;
    if (w >= d) {
        if (cc < 12)
            v = c8x[((size_t)(b * 12 + cc) * HOo + h) * WOo + w];
        else
            v = c8x[((size_t)((b + 2) * 12 + (cc - 12)) * HOo + h) * WOo + (w - d)];
    }
    out[(((size_t)(b * 32 + 8 + cc) * Dd + d) * HOo + h) * WOo + w] = v;
}

// ---------------------------------------------------------------------------
// Launch — cat chain forked onto a second stream (capture-legal fork/join)
// so it overlaps the big gwc chain in the graph.
// ---------------------------------------------------------------------------
extern "C" void kernel_launch(void* const* d_in, const int* in_sizes, int n_in,
                              void* d_out, int out_size)
{
    const float* gx  = (const float*)d_in[0];
    const float* cx  = (const float*)d_in[1];
    const float* gw1 = (const float*)d_in[2];
    const float* gbg = (const float*)d_in[3];
    const float* gbb = (const float*)d_in[4];
    const float* gbm = (const float*)d_in[5];
    const float* gbv = (const float*)d_in[6];
    const float* gw2 = (const float*)d_in[7];
    const float* cw1 = (const float*)d_in[8];
    const float* cbg = (const float*)d_in[9];
    const float* cbb = (const float*)d_in[10];
    const float* cbm = (const float*)d_in[11];
    const float* cbv = (const float*)d_in[12];
    const float* cw2 = (const float*)d_in[13];
    float* out = (float*)d_out;

    float *y1, *g8x, *y2, *c8x, *msk;
    cudaGetSymbolAddress((void**)&y1,  d_y1);
    cudaGetSymbolAddress((void**)&g8x, d_g8x);
    cudaGetSymbolAddress((void**)&y2,  d_y2);
    cudaGetSymbolAddress((void**)&c8x, d_c8x);
    cudaGetSymbolAddress((void**)&msk, d_msk);

    static cudaStream_t s2 = nullptr;
    static cudaEvent_t ev_fork = nullptr, ev_join = nullptr;
    if (s2 == nullptr) {
        cudaStreamCreateWithFlags(&s2, cudaStreamNonBlocking);
        cudaEventCreateWithFlags(&ev_fork, cudaEventDisableTiming);
        cudaEventCreateWithFlags(&ev_join, cudaEventDisableTiming);
        cudaFuncSetAttribute(conv_gwc_mma, cudaFuncAttributeMaxDynamicSharedMemorySize, SM_CONV);
        cudaFuncSetAttribute(gemm_logits_mma, cudaFuncAttributeMaxDynamicSharedMemorySize, SM_LOG);
    }

    // Fork the independent cat chain onto s2.
    cudaEventRecord(ev_fork, 0);
    cudaStreamWaitEvent(s2, ev_fork, 0);

    // --- cat chain (stream s2) ---
    conv_cat_direct<<<(cfg::B * cfg::HW) / 128, 256, 0, s2>>>(
        cx, cw1, cbg, cbb, cbm, cbv, y2);
    mask_softmax_unfold<12, 24, 12, 1, 12><<<dim3(3, 80, 4), 144, 0, s2>>>(
        y2, cw2, cx, c8x);
    cat_volume_kernel<<<(2 * 24 * cfg::Dd * cfg::HW + 255) / 256, 256, 0, s2>>>(c8x, out);
    cudaEventRecord(ev_join, s2);

    // --- gwc chain (legacy stream) ---
    wprep_kernel<<<(cfg::NCHUNK * 192 * 32 + 255) / 256, 256>>>(gw1);
    wprep2_kernel<<<(6 * 144 * 32 + 255) / 256, 256>>>(gw2);
    conv_gwc_mma<<<dim3(360, 2), 256, SM_CONV>>>(gx, gbg, gbb, gbm, gbv, y1);
    gemm_logits_mma<<<360, 384, SM_LOG>>>(y1, msk);
    softmax_unfold_gwc<<<dim3(3, 80, 4), 192>>>(msk, gx, g8x);
    gwc_volume_kernel<<<dim3(40, 8, 2), dim3(144, 2)>>>(g8x, out);

    // Join: output complete only after both chains.
    cudaStreamWaitEvent(0, ev_join, 0);
}